// round 3
// baseline (speedup 1.0000x reference)
#include <cuda_runtime.h>

#define CH 4
#define HDIM 1025
#define WDIM 1024
#define NTOT (CH*HDIM*WDIM)
#define STRIDE_T 1028
#define NT_T (CH*WDIM*STRIDE_T)
#define SEG 32
#define BS 128

// scratch (allocation-free rule: __device__ globals)
__device__ __align__(16) float g_ST[NT_T];      // S transposed: (4, 1024, STRIDE_T) cols 0..1024 valid
__device__ __align__(16) float g_harmT[NT_T];   // harmonic median, transposed+padded layout
__device__ __align__(16) float g_perc[NTOT];    // percussive median, natural layout

__device__ __forceinline__ float finf() { return __int_as_float(0x7f800000); }

__device__ __forceinline__ void cas2(float2& a, float2& b) {
    float lx = fminf(a.x, b.x), hx = fmaxf(a.x, b.x);
    float ly = fminf(a.y, b.y), hy = fmaxf(a.y, b.y);
    a.x = lx; a.y = ly; b.x = hx; b.y = hy;
}

// Batcher odd-even mergesort over 32 float2 slots (each .x/.y lane independent)
__device__ __forceinline__ void sort32_2(float2* a) {
#pragma unroll
    for (int p = 1; p < 32; p <<= 1)
#pragma unroll
        for (int k = p; k >= 1; k >>= 1)
#pragma unroll
            for (int j = k & (p - 1); j + k < 32; j += 2 * k)
#pragma unroll
                for (int i = 0; i < k; ++i)
                    if (i + j + k < 32)
                        if (((i + j) / (2 * p)) == ((i + j + k) / (2 * p)))
                            cas2(a[i + j], a[i + j + k]);
}

// ---------------- transpose: S (4,1025,1024) -> ST (4,1024,STRIDE_T) ----------------
__global__ void __launch_bounds__(256) transpose_kernel(const float* __restrict__ S) {
    __shared__ float tile[32][33];
    int ch = blockIdx.z;
    int h0 = blockIdx.y * 32;
    int w0 = blockIdx.x * 32;
    int tx = threadIdx.x, ty = threadIdx.y;   // (32, 8)
    const float* Sp = S + (size_t)ch * HDIM * WDIM;
#pragma unroll
    for (int i = 0; i < 4; ++i) {
        int h = h0 + ty + i * 8;
        if (h < HDIM) tile[ty + i * 8][tx] = Sp[(size_t)h * WDIM + (w0 + tx)];
    }
    __syncthreads();
    float* STp = g_ST + (size_t)ch * WDIM * STRIDE_T;
#pragma unroll
    for (int i = 0; i < 4; ++i) {
        int w = w0 + ty + i * 8;
        int h = h0 + tx;
        if (h < HDIM) STp[(size_t)w * STRIDE_T + h] = tile[tx][ty + i * 8];
    }
}

// ---------------- column median-31 (zero padded), 2 columns/thread ----------------
// A viewed as (4, R, STRIDE); median along R for column pairs (2*pr, 2*pr+1).
// Window v[0..30] sorted ascending per lane (.x/.y); v[31] sentinel slot.
template<int R, int STRIDE>
__global__ void __launch_bounds__(BS, 4) colmed2_kernel(const float* __restrict__ A,
                                                        float* __restrict__ Out,
                                                        int nPairs, int nJobs) {
    int job = blockIdx.x * BS + threadIdx.x;
    if (job >= nJobs) return;
    const int nCols = 4 * nPairs;
    int seg = job / nCols;
    int rem = job - seg * nCols;
    int ch = rem / nPairs;
    int pr = rem - ch * nPairs;
    int c = 2 * pr;
    const float* in = A + (size_t)ch * R * STRIDE + c;
    float* out = Out + (size_t)ch * R * STRIDE + c;
    int r0 = seg * SEG;
    int r1 = min(r0 + SEG, R);

    float2 v[32];
    // prologue: window(r0) = padded rows r0-15 .. r0+15, sorted
#pragma unroll
    for (int i = 0; i < 31; ++i) {
        int p = r0 - 15 + i;
        float2 x = make_float2(0.f, 0.f);
        if (p >= 0 && p < R) x = *(const float2*)(in + (size_t)p * STRIDE);
        v[i] = x;
    }
    v[31] = make_float2(finf(), finf());
    sort32_2(v);

    for (int r = r0; r < r1; ++r) {
        *(float2*)(out + (size_t)r * STRIDE) = v[15];
        // slide window(r) -> window(r+1)
        int ro = r - 15, ri = r + 16;
        float2 xo = make_float2(0.f, 0.f);
        float2 xi = make_float2(0.f, 0.f);
        if (ro >= 0) xo = *(const float2*)(in + (size_t)ro * STRIDE);
        if (ri < R)  xi = *(const float2*)(in + (size_t)ri * STRIDE);
        // delete xo (present bit-exactly): shift-left from its slot, INF fills top
#pragma unroll
        for (int i = 0; i < 30; ++i) {
            v[i].x = (v[i].x < xo.x) ? v[i].x : v[i + 1].x;
            v[i].y = (v[i].y < xo.y) ? v[i].y : v[i + 1].y;
        }
        v[30].x = (v[30].x < xo.x) ? v[30].x : finf();
        v[30].y = (v[30].y < xo.y) ? v[30].y : finf();
        // insert xi: min/max cascade; the INF sentinel pops out the top
        float tx = xi.x, ty = xi.y;
#pragma unroll
        for (int i = 0; i < 31; ++i) {
            float nx = fminf(v[i].x, tx); tx = fmaxf(v[i].x, tx); v[i].x = nx;
            float ny = fminf(v[i].y, ty); ty = fmaxf(v[i].y, ty); v[i].y = ny;
        }
    }
}

// ---------------- softmask + outputs (de-transposes harm via shared tile) ----------------
// mask_h = h^2/(h^2+p^2); mask_p = p^2/(h^2+p^2)
__global__ void __launch_bounds__(256) mask_kernel(const float* __restrict__ S,
                                                   float* __restrict__ outA,
                                                   float* __restrict__ outB) {
    __shared__ float tile[32][33];
    int ch = blockIdx.z;
    int h0 = blockIdx.y * 32;
    int w0 = blockIdx.x * 32;
    int tx = threadIdx.x, ty = threadIdx.y;   // (32, 8)
    const float* HT = g_harmT + (size_t)ch * WDIM * STRIDE_T;
#pragma unroll
    for (int i = 0; i < 4; ++i) {
        int wl = ty + i * 8;
        int h = h0 + tx;
        if (h < HDIM) tile[wl][tx] = HT[(size_t)(w0 + wl) * STRIDE_T + h];
    }
    __syncthreads();
    size_t chOff = (size_t)ch * HDIM * WDIM;
#pragma unroll
    for (int i = 0; i < 4; ++i) {
        int h = h0 + ty + i * 8;
        if (h < HDIM) {
            int w = w0 + tx;
            size_t idx = chOff + (size_t)h * WDIM + w;
            float hv = tile[tx][ty + i * 8];
            float pv = g_perc[idx];
            float s = S[idx];
            float hh = hv * hv, pp = pv * pv;
            float rcp = 1.0f / fmaxf(hh + pp, 1e-30f);
            outA[idx] = s * hh * rcp;
            outB[idx] = s * pp * rcp;
        }
    }
}

extern "C" void kernel_launch(void* const* d_in, const int* in_sizes, int n_in,
                              void* d_out, int out_size) {
    const float* S = (const float*)d_in[0];
    float* out = (float*)d_out;

    float* ST;    cudaGetSymbolAddress((void**)&ST, g_ST);
    float* harmT; cudaGetSymbolAddress((void**)&harmT, g_harmT);
    float* perc;  cudaGetSymbolAddress((void**)&perc, g_perc);

    // 1) transpose S into ST (padded stride)
    transpose_kernel<<<dim3(WDIM / 32, (HDIM + 31) / 32, CH), dim3(32, 8)>>>(S);

    // 2) harmonic: median along original W == column median on ST
    //    R=1024 rows, 1025 valid cols -> 513 pairs (last pair's .y is pad, harmless)
    {
        const int nSegs = (WDIM + SEG - 1) / SEG;          // 32
        const int nPairs = (HDIM + 1) / 2;                 // 513
        const int nJobs = nSegs * 4 * nPairs;
        colmed2_kernel<WDIM, STRIDE_T><<<(nJobs + BS - 1) / BS, BS>>>(ST, harmT, nPairs, nJobs);
    }

    // 3) percussive: median along H, natural layout: R=1025 rows, 1024 cols -> 512 pairs
    {
        const int nSegs = (HDIM + SEG - 1) / SEG;          // 33
        const int nPairs = WDIM / 2;                       // 512
        const int nJobs = nSegs * 4 * nPairs;
        colmed2_kernel<HDIM, WDIM><<<(nJobs + BS - 1) / BS, BS>>>(S, perc, nPairs, nJobs);
    }

    // 4) masks + both outputs
    mask_kernel<<<dim3(WDIM / 32, (HDIM + 31) / 32, CH), dim3(32, 8)>>>(S, out, out + NTOT);
}

// round 4
// speedup vs baseline: 1.3310x; 1.3310x over previous
#include <cuda_runtime.h>

#define CH 4
#define HDIM 1025
#define WDIM 1024
#define NTOT (CH*HDIM*WDIM)
#define STRIDE_T 1028
#define NT_T (CH*WDIM*STRIDE_T)
#define SEG 64
#define BS 128

// fused colmed grid constants
#define NJOBS_H (16 * CH * HDIM)            /* 16 segs * 4 ch * 1025 cols = 65600 */
#define BLOCKS_H ((NJOBS_H + BS - 1) / BS)  /* 513 */
#define NJOBS_P (17 * CH * WDIM)            /* 17 segs * 4 ch * 1024 cols = 69632 */
#define BLOCKS_P ((NJOBS_P + BS - 1) / BS)  /* 544 */

// scratch (allocation-free rule: __device__ globals)
__device__ __align__(16) float g_ST[NT_T];      // S transposed: (4, 1024, STRIDE_T), cols 0..1024 valid
__device__ __align__(16) float g_harmT[NT_T];   // harmonic median, transposed+padded layout
__device__ __align__(16) float g_perc[NTOT];    // percussive median, natural layout

__device__ __forceinline__ float finf() { return __int_as_float(0x7f800000); }

__device__ __forceinline__ void cas(float& a, float& b) {
    float lo = fminf(a, b);
    float hi = fmaxf(a, b);
    a = lo; b = hi;
}

// Batcher odd-even mergesort, n=32, fully unrolled -> registers
__device__ __forceinline__ void sort32(float* a) {
#pragma unroll
    for (int p = 1; p < 32; p <<= 1)
#pragma unroll
        for (int k = p; k >= 1; k >>= 1)
#pragma unroll
            for (int j = k & (p - 1); j + k < 32; j += 2 * k)
#pragma unroll
                for (int i = 0; i < k; ++i)
                    if (i + j + k < 32)
                        if (((i + j) / (2 * p)) == ((i + j + k) / (2 * p)))
                            cas(a[i + j], a[i + j + k]);
}

// ---------------- transpose: S (4,1025,1024) -> ST (4,1024,STRIDE_T) ----------------
__global__ void __launch_bounds__(256) transpose_kernel(const float* __restrict__ S) {
    __shared__ float tile[32][33];
    int ch = blockIdx.z;
    int h0 = blockIdx.y * 32;
    int w0 = blockIdx.x * 32;
    int tx = threadIdx.x, ty = threadIdx.y;   // (32, 8)
    const float* Sp = S + (size_t)ch * HDIM * WDIM;
#pragma unroll
    for (int i = 0; i < 4; ++i) {
        int h = h0 + ty + i * 8;
        if (h < HDIM) tile[ty + i * 8][tx] = Sp[(size_t)h * WDIM + (w0 + tx)];
    }
    __syncthreads();
    float* STp = g_ST + (size_t)ch * WDIM * STRIDE_T;
#pragma unroll
    for (int i = 0; i < 4; ++i) {
        int w = w0 + ty + i * 8;
        int h = h0 + tx;
        if (h < HDIM) STp[(size_t)w * STRIDE_T + h] = tile[tx][ty + i * 8];
    }
}

// ---------------- sliding sorted-window median-31 over one column segment --------------
// Window v[0..30] sorted ascending; v[31] is the INF sentinel slot. Zero padding at
// both ends. Loads for the next slide are prefetched before the current cascade so
// L2 latency hides behind ~250 cycles of alu work.
template<int R, int STRIDE>
__device__ __forceinline__ void colmed_run(const float* __restrict__ in,
                                           float* __restrict__ out,
                                           int r0, int r1) {
    float v[32];
#pragma unroll
    for (int i = 0; i < 31; ++i) {
        int p = r0 - 15 + i;
        float x = 0.f;
        if (p >= 0 && p < R) x = in[(size_t)p * STRIDE];
        v[i] = x;
    }
    v[31] = finf();
    sort32(v);

    // prefetch the first slide pair: rows (r0-15) out, (r0+16) in
    float xo = (r0 >= 15) ? in[(size_t)(r0 - 15) * STRIDE] : 0.f;
    float xi = (r0 + 16 < R) ? in[(size_t)(r0 + 16) * STRIDE] : 0.f;

#pragma unroll 2
    for (int r = r0; r < r1; ++r) {
        out[(size_t)r * STRIDE] = v[15];
        float cxo = xo, cxi = xi;
        // prefetch next pair (rows r-14 and r+17) before the cascade
        int ro = r - 14, ri = r + 17;
        xo = (ro >= 0) ? in[(size_t)ro * STRIDE] : 0.f;   // ro < R always within segs
        xi = (ri < R) ? in[(size_t)ri * STRIDE] : 0.f;
        // delete cxo (present bit-exactly): shift-left from its slot, INF fills top
#pragma unroll
        for (int i = 0; i < 30; ++i) v[i] = (v[i] < cxo) ? v[i] : v[i + 1];
        v[30] = (v[30] < cxo) ? v[30] : finf();
        // insert cxi: min/max cascade; the INF sentinel pops out the top
        float t = cxi;
#pragma unroll
        for (int i = 0; i < 31; ++i) {
            float lo = fminf(v[i], t);
            t = fmaxf(v[i], t);
            v[i] = lo;
        }
    }
}

// ---------------- fused: harmonic (on ST) + percussive (on S) in one launch ------------
__global__ void __launch_bounds__(BS, 6) colmed_fused_kernel(const float* __restrict__ S) {
    if (blockIdx.x < BLOCKS_H) {
        int job = blockIdx.x * BS + threadIdx.x;
        if (job >= NJOBS_H) return;
        const int nCols = CH * HDIM;
        int seg = job / nCols;
        int rem = job - seg * nCols;
        int ch = rem / HDIM;
        int c = rem - ch * HDIM;
        const float* in = g_ST + (size_t)ch * WDIM * STRIDE_T + c;
        float* out = g_harmT + (size_t)ch * WDIM * STRIDE_T + c;
        int r0 = seg * SEG;
        colmed_run<WDIM, STRIDE_T>(in, out, r0, min(r0 + SEG, WDIM));
    } else {
        int job = (blockIdx.x - BLOCKS_H) * BS + threadIdx.x;
        if (job >= NJOBS_P) return;
        const int nCols = CH * WDIM;
        int seg = job / nCols;
        int rem = job - seg * nCols;
        int ch = rem / WDIM;
        int c = rem - ch * WDIM;
        const float* in = S + (size_t)ch * HDIM * WDIM + c;
        float* out = g_perc + (size_t)ch * HDIM * WDIM + c;
        int r0 = seg * SEG;
        colmed_run<HDIM, WDIM>(in, out, r0, min(r0 + SEG, HDIM));
    }
}

// ---------------- softmask + outputs (de-transposes harm via shared tile) ----------------
// mask_h = h^2/(h^2+p^2); mask_p = p^2/(h^2+p^2)
__global__ void __launch_bounds__(256) mask_kernel(const float* __restrict__ S,
                                                   float* __restrict__ outA,
                                                   float* __restrict__ outB) {
    __shared__ float tile[32][33];
    int ch = blockIdx.z;
    int h0 = blockIdx.y * 32;
    int w0 = blockIdx.x * 32;
    int tx = threadIdx.x, ty = threadIdx.y;   // (32, 8)
    const float* HT = g_harmT + (size_t)ch * WDIM * STRIDE_T;
#pragma unroll
    for (int i = 0; i < 4; ++i) {
        int wl = ty + i * 8;
        int h = h0 + tx;
        if (h < HDIM) tile[wl][tx] = HT[(size_t)(w0 + wl) * STRIDE_T + h];
    }
    __syncthreads();
    size_t chOff = (size_t)ch * HDIM * WDIM;
#pragma unroll
    for (int i = 0; i < 4; ++i) {
        int h = h0 + ty + i * 8;
        if (h < HDIM) {
            int w = w0 + tx;
            size_t idx = chOff + (size_t)h * WDIM + w;
            float hv = tile[tx][ty + i * 8];
            float pv = g_perc[idx];
            float s = S[idx];
            float hh = hv * hv, pp = pv * pv;
            float rcp = 1.0f / fmaxf(hh + pp, 1e-30f);
            outA[idx] = s * hh * rcp;
            outB[idx] = s * pp * rcp;
        }
    }
}

extern "C" void kernel_launch(void* const* d_in, const int* in_sizes, int n_in,
                              void* d_out, int out_size) {
    const float* S = (const float*)d_in[0];
    float* out = (float*)d_out;

    // 1) transpose S into ST (padded stride)
    transpose_kernel<<<dim3(WDIM / 32, (HDIM + 31) / 32, CH), dim3(32, 8)>>>(S);

    // 2) both median filters in one launch
    colmed_fused_kernel<<<BLOCKS_H + BLOCKS_P, BS>>>(S);

    // 3) masks + both outputs
    mask_kernel<<<dim3(WDIM / 32, (HDIM + 31) / 32, CH), dim3(32, 8)>>>(S, out, out + NTOT);
}

// round 5
// speedup vs baseline: 1.3744x; 1.0326x over previous
#include <cuda_runtime.h>

#define CH 4
#define HDIM 1025
#define WDIM 1024
#define NTOT (CH*HDIM*WDIM)
#define STRIDE_T 1028
#define NT_T (CH*WDIM*STRIDE_T)
#define SEG 64
#define BS 128

// fused colmed grid constants
#define NJOBS_H (16 * CH * HDIM)            /* 16 segs * 4 ch * 1025 cols = 65600 */
#define BLOCKS_H ((NJOBS_H + BS - 1) / BS)  /* 513 */
#define NJOBS_P (17 * CH * WDIM)            /* 17 segs * 4 ch * 1024 cols = 69632 */
#define BLOCKS_P ((NJOBS_P + BS - 1) / BS)  /* 544 */

// scratch (allocation-free rule: __device__ globals)
__device__ __align__(16) float g_ST[NT_T];      // S transposed: (4, 1024, STRIDE_T), cols 0..1024 valid
__device__ __align__(16) float g_harmT[NT_T];   // harmonic median, transposed+padded layout
__device__ __align__(16) float g_perc[NTOT];    // percussive median, natural layout

__device__ __forceinline__ float finf() { return __int_as_float(0x7f800000); }

__device__ __forceinline__ void cas(float& a, float& b) {
    float lo = fminf(a, b);
    float hi = fmaxf(a, b);
    a = lo; b = hi;
}

// Batcher odd-even mergesort, n=32, fully unrolled -> registers
__device__ __forceinline__ void sort32(float* a) {
#pragma unroll
    for (int p = 1; p < 32; p <<= 1)
#pragma unroll
        for (int k = p; k >= 1; k >>= 1)
#pragma unroll
            for (int j = k & (p - 1); j + k < 32; j += 2 * k)
#pragma unroll
                for (int i = 0; i < k; ++i)
                    if (i + j + k < 32)
                        if (((i + j) / (2 * p)) == ((i + j + k) / (2 * p)))
                            cas(a[i + j], a[i + j + k]);
}

// ---------------- transpose: S (4,1025,1024) -> ST (4,1024,STRIDE_T) ----------------
__global__ void __launch_bounds__(256) transpose_kernel(const float* __restrict__ S) {
    __shared__ float tile[32][33];
    int ch = blockIdx.z;
    int h0 = blockIdx.y * 32;
    int w0 = blockIdx.x * 32;
    int tx = threadIdx.x, ty = threadIdx.y;   // (32, 8)
    const float* Sp = S + (size_t)ch * HDIM * WDIM;
#pragma unroll
    for (int i = 0; i < 4; ++i) {
        int h = h0 + ty + i * 8;
        if (h < HDIM) tile[ty + i * 8][tx] = Sp[(size_t)h * WDIM + (w0 + tx)];
    }
    __syncthreads();
    float* STp = g_ST + (size_t)ch * WDIM * STRIDE_T;
#pragma unroll
    for (int i = 0; i < 4; ++i) {
        int w = w0 + ty + i * 8;
        int h = h0 + tx;
        if (h < HDIM) STp[(size_t)w * STRIDE_T + h] = tile[tx][ty + i * 8];
    }
}

// ---------------- sliding sorted-window median-31 over one column segment --------------
// Window v[0..30] sorted ascending (v[31] = INF sentinel for the prologue sort).
// Slide = branch-free PARALLEL replace: with d[i] = delete-xo = (v[i]<xo ? v[i] : v[i+1]),
// insertion of xi is per-slot independent: new[i] = min(max(d[i-1], xi), d[i]).
// Computed in one descending sweep; the d-carry is a register rename, so the
// dataflow critical path is ~2 ops (vs the 31-deep serial cascade it replaces).
template<int R, int STRIDE>
__device__ __forceinline__ void colmed_run(const float* __restrict__ in,
                                           float* __restrict__ out,
                                           int r0, int r1) {
    float v[32];
#pragma unroll
    for (int i = 0; i < 31; ++i) {
        int p = r0 - 15 + i;
        float x = 0.f;
        if (p >= 0 && p < R) x = in[(size_t)p * STRIDE];
        v[i] = x;
    }
    v[31] = finf();
    sort32(v);

    // prefetch the first slide pair: rows (r0-15) out, (r0+16) in
    float xo = (r0 >= 15) ? in[(size_t)(r0 - 15) * STRIDE] : 0.f;
    float xi = (r0 + 16 < R) ? in[(size_t)(r0 + 16) * STRIDE] : 0.f;

#pragma unroll 2
    for (int r = r0; r < r1; ++r) {
        out[(size_t)r * STRIDE] = v[15];
        float cxo = xo, cxi = xi;
        // prefetch next pair (rows r-14 and r+17) before the slide math
        int ro = r - 14, ri = r + 17;
        xo = (ro >= 0) ? in[(size_t)ro * STRIDE] : 0.f;   // ro < R always within segs
        xi = (ri < R) ? in[(size_t)ri * STRIDE] : 0.f;

        // combined delete(cxo)+insert(cxi), all slots independent
        float dc = (v[30] < cxo) ? v[30] : finf();        // d[30] (INF fills top)
#pragma unroll
        for (int i = 30; i >= 1; --i) {
            float dp = (v[i - 1] < cxo) ? v[i - 1] : v[i];  // d[i-1]
            v[i] = fminf(fmaxf(dp, cxi), dc);
            dc = dp;
        }
        v[0] = fminf(cxi, dc);                            // d[-1] = -inf
    }
}

// ---------------- fused: harmonic (on ST) + percussive (on S) in one launch ------------
__global__ void __launch_bounds__(BS, 6) colmed_fused_kernel(const float* __restrict__ S) {
    if (blockIdx.x < BLOCKS_H) {
        int job = blockIdx.x * BS + threadIdx.x;
        if (job >= NJOBS_H) return;
        const int nCols = CH * HDIM;
        int seg = job / nCols;
        int rem = job - seg * nCols;
        int ch = rem / HDIM;
        int c = rem - ch * HDIM;
        const float* in = g_ST + (size_t)ch * WDIM * STRIDE_T + c;
        float* out = g_harmT + (size_t)ch * WDIM * STRIDE_T + c;
        int r0 = seg * SEG;
        colmed_run<WDIM, STRIDE_T>(in, out, r0, min(r0 + SEG, WDIM));
    } else {
        int job = (blockIdx.x - BLOCKS_H) * BS + threadIdx.x;
        if (job >= NJOBS_P) return;
        const int nCols = CH * WDIM;
        int seg = job / nCols;
        int rem = job - seg * nCols;
        int ch = rem / WDIM;
        int c = rem - ch * WDIM;
        const float* in = S + (size_t)ch * HDIM * WDIM + c;
        float* out = g_perc + (size_t)ch * HDIM * WDIM + c;
        int r0 = seg * SEG;
        colmed_run<HDIM, WDIM>(in, out, r0, min(r0 + SEG, HDIM));
    }
}

// ---------------- softmask + outputs (de-transposes harm via shared tile) ----------------
// mask_h = h^2/(h^2+p^2); mask_p = p^2/(h^2+p^2)
__global__ void __launch_bounds__(256) mask_kernel(const float* __restrict__ S,
                                                   float* __restrict__ outA,
                                                   float* __restrict__ outB) {
    __shared__ float tile[32][33];
    int ch = blockIdx.z;
    int h0 = blockIdx.y * 32;
    int w0 = blockIdx.x * 32;
    int tx = threadIdx.x, ty = threadIdx.y;   // (32, 8)
    const float* HT = g_harmT + (size_t)ch * WDIM * STRIDE_T;
#pragma unroll
    for (int i = 0; i < 4; ++i) {
        int wl = ty + i * 8;
        int h = h0 + tx;
        if (h < HDIM) tile[wl][tx] = HT[(size_t)(w0 + wl) * STRIDE_T + h];
    }
    __syncthreads();
    size_t chOff = (size_t)ch * HDIM * WDIM;
    int w = w0 + tx;
    // hoist all natural-layout loads (8 outstanding LDG -> latency hidden)
    float sv[4], pv[4];
    bool ok[4];
#pragma unroll
    for (int i = 0; i < 4; ++i) {
        int h = h0 + ty + i * 8;
        ok[i] = (h < HDIM);
        size_t idx = chOff + (size_t)h * WDIM + w;
        sv[i] = ok[i] ? S[idx] : 0.f;
        pv[i] = ok[i] ? g_perc[idx] : 0.f;
    }
#pragma unroll
    for (int i = 0; i < 4; ++i) {
        if (ok[i]) {
            int h = h0 + ty + i * 8;
            size_t idx = chOff + (size_t)h * WDIM + w;
            float hv = tile[tx][ty + i * 8];
            float hh = hv * hv, pp = pv[i] * pv[i];
            float rcp = 1.0f / fmaxf(hh + pp, 1e-30f);
            outA[idx] = sv[i] * hh * rcp;
            outB[idx] = sv[i] * pp * rcp;
        }
    }
}

extern "C" void kernel_launch(void* const* d_in, const int* in_sizes, int n_in,
                              void* d_out, int out_size) {
    const float* S = (const float*)d_in[0];
    float* out = (float*)d_out;

    // 1) transpose S into ST (padded stride)
    transpose_kernel<<<dim3(WDIM / 32, (HDIM + 31) / 32, CH), dim3(32, 8)>>>(S);

    // 2) both median filters in one launch
    colmed_fused_kernel<<<BLOCKS_H + BLOCKS_P, BS>>>(S);

    // 3) masks + both outputs
    mask_kernel<<<dim3(WDIM / 32, (HDIM + 31) / 32, CH), dim3(32, 8)>>>(S, out, out + NTOT);
}